// round 13
// baseline (speedup 1.0000x reference)
#include <cuda_runtime.h>
#include <cstdint>

// Problem constants
#define BB 4
#define SS 4096
#define DD 2048
#define LL 3
#define TRIPLE (3 * DD)
#define MTOT (BB * SS)          // 16384

// GEMM tiling: CTA 128x128, 4 warps (2x2), warp tile 64x64, BK=32,
// 3-stage cp.async, 2 CTAs/SM, single barrier per k-tile.
// Persistent: 296 CTAs loop over tiles; prefetch crosses tile boundaries.
#define BM 128
#define BN 128
#define BK 32
#define NSTAGE 3
#define AST 36
#define BST 264
#define A_SM (BM * AST)         // 4608 floats
#define B_SM (16 * BST)         // 4224 floats
#define STG_FLT (A_SM + B_SM)   // 8832 floats
#define SMEM_BYTES (NSTAGE * STG_FLT * 4)   // 105984 B
#define NPERS 296

// Scratch (__device__ globals: allocation-free rule)
__device__ float g_Bx[(size_t)MTOT * DD];        // B_gate*x_proj (GEMM1 epilogue)
__device__ float g_Cg[(size_t)MTOT * DD];        // C_gate
__device__ float g_y[(size_t)MTOT * DD];         // GEMM2 A (tf32-rounded)
__device__ float g_xc[(size_t)MTOT * DD];        // x tf32-rounded
__device__ float g_Win[(size_t)DD * TRIPLE];     // W_in  remapped+interleaved [K/2][2N]
__device__ float g_Wout[(size_t)DD * DD];        // W_out interleaved [K/2][2N]

__device__ __forceinline__ float f2tf32(float x) {
    float r;
    asm("cvt.rna.tf32.f32 %0, %1;" : "=f"(r) : "f"(x));
    return r;
}

__device__ __forceinline__ uint32_t smem_u32(const void* p) {
    uint32_t a;
    asm("{ .reg .u64 t; cvta.to.shared.u64 t, %1; cvt.u32.u64 %0, t; }" : "=r"(a) : "l"(p));
    return a;
}

#define CP_ASYNC16(dst, src) \
    asm volatile("cp.async.cg.shared.global [%0], [%1], 16;" :: "r"(dst), "l"(src))
#define CP_COMMIT() asm volatile("cp.async.commit_group;" ::: "memory")
#define CP_WAIT1()  asm volatile("cp.async.wait_group 1;" ::: "memory")

__device__ __forceinline__ void mma_tf32(float c[4], const uint32_t a[4], const uint32_t b[2]) {
    asm volatile(
        "mma.sync.aligned.m16n8k8.row.col.f32.tf32.tf32.f32 "
        "{%0,%1,%2,%3}, {%4,%5,%6,%7}, {%8,%9}, {%0,%1,%2,%3};"
        : "+f"(c[0]), "+f"(c[1]), "+f"(c[2]), "+f"(c[3])
        : "r"(a[0]), "r"(a[1]), "r"(a[2]), "r"(a[3]), "r"(b[0]), "r"(b[1]));
}

// ---------------------------------------------------------------------------
// Persistent TF32 mma.sync GEMM. A row-major (tf32-pre-rounded),
// B pre-interleaved [K/2][2N]. Tiles rastered n-fastest (tile % GX).
// MODE 0: plain C[M][N]. MODE 1: gated GEMM1 epilogue (Bx / C_gate split).
// ---------------------------------------------------------------------------
template <int MODE>
__global__ __launch_bounds__(128, 2)
void tf32_gemm_p(const float* __restrict__ A, const float* __restrict__ B,
                 float* __restrict__ C, float* __restrict__ CBx,
                 float* __restrict__ CCg, int N, int K, int NTILES, int GX) {
    extern __shared__ float sm[];
    const uint32_t smb = smem_u32(sm);

    const int tid    = threadIdx.x;
    const int wid    = tid >> 5;
    const int lane   = tid & 31;
    const int warp_m = wid >> 1;      // 0..1
    const int warp_n = wid & 1;       // 0..1
    const int lr     = lane >> 2;     // 0..7
    const int lc     = lane & 3;      // 0..3

    const size_t brs = 2 * (size_t)N;   // interleaved B row stride (floats)

    const int arow0 = tid >> 3;
    const int akc   = (tid & 7) * 4;
    const int brw   = tid >> 3;
    const int bcc   = (tid & 7) * 4;

    auto issue = [&](const float* Ap, const float* Bp, int kt, int buf) {
        uint32_t as = smb + (uint32_t)buf * STG_FLT * 4;
        uint32_t bs = as + A_SM * 4;
        #pragma unroll
        for (int i = 0; i < 8; i++) {
            int m = arow0 + i * 16;
            CP_ASYNC16(as + (uint32_t)(m * AST + akc) * 4,
                       Ap + (size_t)m * K + kt * BK + akc);
        }
        const float* bsrc = Bp + (size_t)(16 * kt + brw) * brs;
        #pragma unroll
        for (int i = 0; i < 8; i++) {
            int c = bcc + i * 32;
            CP_ASYNC16(bs + (uint32_t)(brw * BST + c) * 4, bsrc + c);
        }
    };

    int t = blockIdx.x;
    if (t >= NTILES) return;

    const float* Ap = A + (size_t)(t / GX) * BM * K;
    const float* Bp = B + 2 * (size_t)((t % GX) * BN);

    // Initial pipeline fill (once per CTA, not per tile)
    issue(Ap, Bp, 0, 0); CP_COMMIT();
    issue(Ap, Bp, 1, 1); CP_COMMIT();

    const int NK = K / BK;
    int buf = 0;

    while (true) {
        const int tn = t + NPERS;
        const bool has_next = tn < NTILES;
        const float* nAp = has_next ? A + (size_t)(tn / GX) * BM * K : Ap;
        const float* nBp = has_next ? B + 2 * (size_t)((tn % GX) * BN) : Bp;

        float acc[4][8][4];
        #pragma unroll
        for (int mi = 0; mi < 4; mi++)
            #pragma unroll
            for (int ni = 0; ni < 8; ni++)
                #pragma unroll
                for (int q = 0; q < 4; q++)
                    acc[mi][ni][q] = 0.0f;

        for (int kt = 0; kt < NK; kt++) {
            CP_WAIT1();
            __syncthreads();

            int nbuf = buf + 2; if (nbuf >= NSTAGE) nbuf -= NSTAGE;
            const int pf = kt + 2;
            if (pf < NK)        issue(Ap, Bp, pf, nbuf);
            else if (has_next)  issue(nAp, nBp, pf - NK, nbuf);
            CP_COMMIT();

            const float* As = sm + (size_t)buf * STG_FLT;
            const float* Bs = As + A_SM;

            #pragma unroll
            for (int ks = 0; ks < 4; ks++) {
                const int k0 = ks * 8;
                uint32_t a[4][4];
                #pragma unroll
                for (int mi = 0; mi < 4; mi++) {
                    const int base = (warp_m * 64 + mi * 16 + lr) * AST + k0 + lc;
                    a[mi][0] = __float_as_uint(As[base]);
                    a[mi][1] = __float_as_uint(As[base + 8 * AST]);
                    a[mi][2] = __float_as_uint(As[base + 4]);
                    a[mi][3] = __float_as_uint(As[base + 8 * AST + 4]);
                }
                uint32_t b[8][2];
                #pragma unroll
                for (int ni = 0; ni < 8; ni++) {
                    const int n = warp_n * 64 + ni * 8 + lr;
                    float2 v = *(const float2*)(Bs + (ks * 4 + lc) * BST + 2 * n);
                    b[ni][0] = __float_as_uint(v.x);
                    b[ni][1] = __float_as_uint(v.y);
                }
                #pragma unroll
                for (int mi = 0; mi < 4; mi++)
                    #pragma unroll
                    for (int ni = 0; ni < 8; ni++)
                        mma_tf32(acc[mi][ni], a[mi], b[ni]);
            }

            if (++buf == NSTAGE) buf = 0;
        }

        // Epilogue for tile t (overlaps with next tile's in-flight prefetch)
        const int brow = (t / GX) * BM;
        const int bcol = (t % GX) * BN;
        if (MODE == 0) {
            #pragma unroll
            for (int mi = 0; mi < 4; mi++) {
                #pragma unroll
                for (int ni = 0; ni < 8; ni++) {
                    const int r0 = brow + warp_m * 64 + mi * 16 + lr;
                    const int c0 = bcol + warp_n * 64 + ni * 8 + lc * 2;
                    *(float2*)(C + (size_t)r0 * N + c0)       = make_float2(acc[mi][ni][0], acc[mi][ni][1]);
                    *(float2*)(C + (size_t)(r0 + 8) * N + c0) = make_float2(acc[mi][ni][2], acc[mi][ni][3]);
                }
            }
        } else if (bcol < 2 * DD) {
            // gated pairs: thread cols (c0, c0+1) = (B_gate_d, x_proj_d)
            #pragma unroll
            for (int mi = 0; mi < 4; mi++) {
                #pragma unroll
                for (int ni = 0; ni < 8; ni++) {
                    const int r0 = brow + warp_m * 64 + mi * 16 + lr;
                    const int d  = (bcol + warp_n * 64 + ni * 8 + lc * 2) >> 1;
                    CBx[(size_t)r0 * DD + d]       = acc[mi][ni][0] * acc[mi][ni][1];
                    CBx[(size_t)(r0 + 8) * DD + d] = acc[mi][ni][2] * acc[mi][ni][3];
                }
            }
        } else {
            #pragma unroll
            for (int mi = 0; mi < 4; mi++) {
                #pragma unroll
                for (int ni = 0; ni < 8; ni++) {
                    const int r0 = brow + warp_m * 64 + mi * 16 + lr;
                    const int c0 = bcol - 2 * DD + warp_n * 64 + ni * 8 + lc * 2;
                    *(float2*)(CCg + (size_t)r0 * DD + c0)       = make_float2(acc[mi][ni][0], acc[mi][ni][1]);
                    *(float2*)(CCg + (size_t)(r0 + 8) * DD + c0) = make_float2(acc[mi][ni][2], acc[mi][ni][3]);
                }
            }
        }

        if (!has_next) break;
        t = tn; Ap = nAp; Bp = nBp;
    }
}

// ---------------------------------------------------------------------------
// Elementwise tf32 rounding (float4 vectorized)
// ---------------------------------------------------------------------------
__global__ void cvt_tf32_kernel(const float* __restrict__ in, float* __restrict__ out,
                                size_t n4) {
    size_t i = (size_t)blockIdx.x * blockDim.x + threadIdx.x;
    if (i >= n4) return;
    float4 v = ((const float4*)in)[i];
    v.x = f2tf32(v.x); v.y = f2tf32(v.y); v.z = f2tf32(v.z); v.w = f2tf32(v.w);
    ((float4*)out)[i] = v;
}

// ---------------------------------------------------------------------------
// W [K][N] -> pair-interleaved [K/2][2N'], optional source-column remap:
//   remap(n) = n<4096 ? (n odd ? 2D+n/2 : n/2) : D + (n-4096)
// out[kb*4+p][2n+h] = tf32(W[kb*8+p+4h][remap(n)]).
// ---------------------------------------------------------------------------
template <int REMAP>
__global__ void wtrans_kernel(const float* __restrict__ in, float* __restrict__ out,
                              int N) {
    __shared__ float s[8][257];
    const int kb = blockIdx.y;
    const int n0 = blockIdx.x * 256;
    const int tid = threadIdx.x;

    int n = n0 + tid;
    int src;
    if (REMAP) {
        src = (n < 2 * DD) ? ((n & 1) ? 2 * DD + (n >> 1) : (n >> 1))
                           : DD + (n - 2 * DD);
    } else {
        src = n;
    }
    #pragma unroll
    for (int j = 0; j < 8; j++)
        s[j][tid] = f2tf32(in[(size_t)(kb * 8 + j) * N + src]);
    __syncthreads();

    const int p  = tid >> 6;        // 0..3
    const int j0 = tid & 63;
    #pragma unroll
    for (int h = 0; h < 2; h++) {
        int j = j0 + h * 64;        // n-pair index 0..127
        float4 v = make_float4(s[p][2 * j], s[p + 4][2 * j],
                               s[p][2 * j + 1], s[p + 4][2 * j + 1]);
        *(float4*)(out + (size_t)(kb * 4 + p) * (2 * N) + 2 * n0 + 4 * j) = v;
    }
}

// ---------------------------------------------------------------------------
// Conv + gate from precomputed Bx and C_gate:
// y = tf32( Cg[s] * (w2*Bx[s] + w1*Bx[s-1] + w0*Bx[s-2]) )
// ---------------------------------------------------------------------------
__global__ void conv_gate_kernel(const float* __restrict__ conv_w,
                                 float* __restrict__ y) {
    const size_t total = (size_t)MTOT * (DD / 4);
    size_t idx = (size_t)blockIdx.x * blockDim.x + threadIdx.x;
    if (idx >= total) return;

    const int    d4 = (int)(idx % (DD / 4));
    const size_t bs = idx / (DD / 4);
    const int    s  = (int)(bs % SS);
    const int    d  = d4 * 4;

    float4 bx0 = *(const float4*)(g_Bx + bs * DD + d);
    float4 bx1 = (s >= 1) ? *(const float4*)(g_Bx + (bs - 1) * DD + d)
                          : make_float4(0.f, 0.f, 0.f, 0.f);
    float4 bx2 = (s >= 2) ? *(const float4*)(g_Bx + (bs - 2) * DD + d)
                          : make_float4(0.f, 0.f, 0.f, 0.f);
    float4 cg  = *(const float4*)(g_Cg + bs * DD + d);

    float o[4];
    const float* b0 = &bx0.x;
    const float* b1 = &bx1.x;
    const float* b2 = &bx2.x;
    const float* cgp = &cg.x;
    #pragma unroll
    for (int j = 0; j < 4; j++) {
        const int dj = d + j;
        const float w0 = conv_w[dj * LL + 0];
        const float w1 = conv_w[dj * LL + 1];
        const float w2 = conv_w[dj * LL + 2];
        float conv = w2 * b0[j] + w1 * b1[j] + w0 * b2[j];
        o[j] = f2tf32(cgp[j] * conv);
    }
    *(float4*)(y + bs * DD + d) = make_float4(o[0], o[1], o[2], o[3]);
}

// ---------------------------------------------------------------------------
extern "C" void kernel_launch(void* const* d_in, const int* in_sizes, int n_in,
                              void* d_out, int out_size) {
    const float* x      = (const float*)d_in[0];
    const float* W_in   = (const float*)d_in[1];
    const float* conv_w = (const float*)d_in[2];
    const float* W_out  = (const float*)d_in[3];
    float*       out    = (float*)d_out;

    float *Bx, *Cg, *y, *xc, *Win, *Wout;
    cudaGetSymbolAddress((void**)&Bx,   g_Bx);
    cudaGetSymbolAddress((void**)&Cg,   g_Cg);
    cudaGetSymbolAddress((void**)&y,    g_y);
    cudaGetSymbolAddress((void**)&xc,   g_xc);
    cudaGetSymbolAddress((void**)&Win,  g_Win);
    cudaGetSymbolAddress((void**)&Wout, g_Wout);

    cudaFuncSetAttribute(tf32_gemm_p<0>, cudaFuncAttributeMaxDynamicSharedMemorySize, SMEM_BYTES);
    cudaFuncSetAttribute(tf32_gemm_p<1>, cudaFuncAttributeMaxDynamicSharedMemorySize, SMEM_BYTES);

    // Pre-passes: tf32 rounding (x) + weight transforms
    {
        size_t n4 = (size_t)MTOT * DD / 4;
        cvt_tf32_kernel<<<(unsigned)((n4 + 255) / 256), 256>>>(x, xc, n4);
        wtrans_kernel<1><<<dim3(TRIPLE / 256, DD / 8), 256>>>(W_in, Win, TRIPLE);
        wtrans_kernel<0><<<dim3(DD / 256, DD / 8), 256>>>(W_out, Wout, DD);
    }

    // GEMM1 (gated, persistent): writes Bx and C_gate directly
    tf32_gemm_p<1><<<NPERS, 128, SMEM_BYTES>>>(
        xc, Win, nullptr, Bx, Cg, TRIPLE, DD, (TRIPLE / BN) * (MTOT / BM), TRIPLE / BN);

    // Conv + gate -> y (tf32-rounded)
    {
        size_t total = (size_t)MTOT * (DD / 4);
        conv_gate_kernel<<<(unsigned)((total + 255) / 256), 256>>>(conv_w, y);
    }

    // GEMM2 (persistent): out = y @ W_out
    tf32_gemm_p<0><<<NPERS, 128, SMEM_BYTES>>>(
        y, Wout, out, nullptr, nullptr, DD, DD, (DD / BN) * (MTOT / BM), DD / BN);
}